// round 1
// baseline (speedup 1.0000x reference)
#include <cuda_runtime.h>
#include <cuda_bf16.h>

// LinearAttention: B=4, N=4096, D=1024, fp32
//   ql = x@Wql, qr = x@Wqr, k = x@Wk, v = x@Wv
//   q  = ql * qr
//   kv[b] = k[b]^T @ v[b]          (D x D per batch)
//   out[b] = q[b] @ kv[b]
//
// Round 0: fp32 register-blocked SGEMM baseline (128x128x8 tile, 8x8/thread).

#define Bv 4
#define Nv 4096
#define Dv 1024
#define BNROWS (Bv * Nv)   // 16384

#define BM 128
#define BN 128
#define BK 8
#define TM 8
#define TN 8
#define NTHREADS 256

// Scratch (device globals per allocation rules)
__device__ float g_QL[(long)BNROWS * Dv];
__device__ float g_QR[(long)BNROWS * Dv];
__device__ float g_K [(long)BNROWS * Dv];
__device__ float g_V [(long)BNROWS * Dv];
__device__ float g_KV[(long)Bv * Dv * Dv];

// ---------------------------------------------------------------------------
// C = A @ B   (A: M x K row-major, lda=K; B: K x N row-major, ldb=N; C: M x N)
// Batched via blockIdx.z with element strides sA/sB/sC.
// All dims assumed multiples of tile sizes (true for this problem).
// ---------------------------------------------------------------------------
__global__ __launch_bounds__(NTHREADS, 2)
void sgemm_nn(const float* __restrict__ Ag, const float* __restrict__ Bg,
              float* __restrict__ Cg, int M, int N, int K,
              long sA, long sB, long sC) {
    const float* A = Ag + (long)blockIdx.z * sA;
    const float* Bp = Bg + (long)blockIdx.z * sB;
    float* C = Cg + (long)blockIdx.z * sC;

    const int bm = blockIdx.y * BM;
    const int bn = blockIdx.x * BN;

    __shared__ float As[BK][BM];
    __shared__ float Bs[BK][BN];

    const int tid = threadIdx.x;
    const int tx = tid % 16;      // 0..15 -> col block
    const int ty = tid / 16;      // 0..15 -> row block

    // A tile load: 128 rows x 8 cols = 1024 floats; 256 threads x float4
    const int a_row = tid >> 1;          // 0..127
    const int a_col = (tid & 1) * 4;     // 0 or 4
    // B tile load: 8 rows x 128 cols; 256 threads x float4
    const int b_row = tid >> 5;          // 0..7
    const int b_col = (tid & 31) * 4;    // 0..124

    float acc[TM][TN];
#pragma unroll
    for (int i = 0; i < TM; i++)
#pragma unroll
        for (int j = 0; j < TN; j++) acc[i][j] = 0.0f;

    for (int k0 = 0; k0 < K; k0 += BK) {
        float4 av = *(const float4*)(A + (long)(bm + a_row) * K + k0 + a_col);
        As[a_col + 0][a_row] = av.x;
        As[a_col + 1][a_row] = av.y;
        As[a_col + 2][a_row] = av.z;
        As[a_col + 3][a_row] = av.w;
        *(float4*)(&Bs[b_row][b_col]) =
            *(const float4*)(Bp + (long)(k0 + b_row) * N + bn + b_col);
        __syncthreads();

#pragma unroll
        for (int kk = 0; kk < BK; kk++) {
            float a[TM], b[TN];
            *(float4*)(&a[0]) = *(const float4*)(&As[kk][ty * TM + 0]);
            *(float4*)(&a[4]) = *(const float4*)(&As[kk][ty * TM + 4]);
            *(float4*)(&b[0]) = *(const float4*)(&Bs[kk][tx * TN + 0]);
            *(float4*)(&b[4]) = *(const float4*)(&Bs[kk][tx * TN + 4]);
#pragma unroll
            for (int i = 0; i < TM; i++)
#pragma unroll
                for (int j = 0; j < TN; j++)
                    acc[i][j] = fmaf(a[i], b[j], acc[i][j]);
        }
        __syncthreads();
    }

#pragma unroll
    for (int i = 0; i < TM; i++) {
        float4* crow = (float4*)(C + (long)(bm + ty * TM + i) * N + bn + tx * TN);
        crow[0] = make_float4(acc[i][0], acc[i][1], acc[i][2], acc[i][3]);
        crow[1] = make_float4(acc[i][4], acc[i][5], acc[i][6], acc[i][7]);
    }
}

// ---------------------------------------------------------------------------
// C = A^T @ B  (A: K x M row-major, lda=M; B: K x N row-major; C: M x N)
// Used for kv[b] = k[b]^T @ v[b]  (M=N=D, K=Nseq)
// ---------------------------------------------------------------------------
__global__ __launch_bounds__(NTHREADS, 2)
void sgemm_tn(const float* __restrict__ Ag, const float* __restrict__ Bg,
              float* __restrict__ Cg, int M, int N, int K,
              long sA, long sB, long sC) {
    const float* A = Ag + (long)blockIdx.z * sA;
    const float* Bp = Bg + (long)blockIdx.z * sB;
    float* C = Cg + (long)blockIdx.z * sC;

    const int bm = blockIdx.y * BM;
    const int bn = blockIdx.x * BN;

    __shared__ float As[BK][BM];
    __shared__ float Bs[BK][BN];

    const int tid = threadIdx.x;
    const int tx = tid % 16;
    const int ty = tid / 16;

    // Both tiles are BK x 128 row-major slabs -> direct float4 copies
    const int r = tid >> 5;           // 0..7
    const int c = (tid & 31) * 4;     // 0..124

    float acc[TM][TN];
#pragma unroll
    for (int i = 0; i < TM; i++)
#pragma unroll
        for (int j = 0; j < TN; j++) acc[i][j] = 0.0f;

    for (int k0 = 0; k0 < K; k0 += BK) {
        *(float4*)(&As[r][c]) =
            *(const float4*)(A + (long)(k0 + r) * M + bm + c);
        *(float4*)(&Bs[r][c]) =
            *(const float4*)(Bp + (long)(k0 + r) * N + bn + c);
        __syncthreads();

#pragma unroll
        for (int kk = 0; kk < BK; kk++) {
            float a[TM], b[TN];
            *(float4*)(&a[0]) = *(const float4*)(&As[kk][ty * TM + 0]);
            *(float4*)(&a[4]) = *(const float4*)(&As[kk][ty * TM + 4]);
            *(float4*)(&b[0]) = *(const float4*)(&Bs[kk][tx * TN + 0]);
            *(float4*)(&b[4]) = *(const float4*)(&Bs[kk][tx * TN + 4]);
#pragma unroll
            for (int i = 0; i < TM; i++)
#pragma unroll
                for (int j = 0; j < TN; j++)
                    acc[i][j] = fmaf(a[i], b[j], acc[i][j]);
        }
        __syncthreads();
    }

#pragma unroll
    for (int i = 0; i < TM; i++) {
        float4* crow = (float4*)(C + (long)(bm + ty * TM + i) * N + bn + tx * TN);
        crow[0] = make_float4(acc[i][0], acc[i][1], acc[i][2], acc[i][3]);
        crow[1] = make_float4(acc[i][4], acc[i][5], acc[i][6], acc[i][7]);
    }
}

// q = ql * qr (in-place into ql), float4-vectorized
__global__ void gate_kernel(float* __restrict__ ql, const float* __restrict__ qr) {
    long i = ((long)blockIdx.x * blockDim.x + threadIdx.x) * 4;
    float4 a = *(float4*)(ql + i);
    float4 b = *(const float4*)(qr + i);
    a.x *= b.x; a.y *= b.y; a.z *= b.z; a.w *= b.w;
    *(float4*)(ql + i) = a;
}

extern "C" void kernel_launch(void* const* d_in, const int* in_sizes, int n_in,
                              void* d_out, int out_size) {
    const float* x   = (const float*)d_in[0];
    const float* wql = (const float*)d_in[1];
    const float* wqr = (const float*)d_in[2];
    const float* wk  = (const float*)d_in[3];
    const float* wv  = (const float*)d_in[4];
    float* out = (float*)d_out;

    float *QL, *QR, *Kb, *Vb, *KV;
    cudaGetSymbolAddress((void**)&QL, g_QL);
    cudaGetSymbolAddress((void**)&QR, g_QR);
    cudaGetSymbolAddress((void**)&Kb, g_K);
    cudaGetSymbolAddress((void**)&Vb, g_V);
    cudaGetSymbolAddress((void**)&KV, g_KV);

    // 1) Projections: (16384 x 1024) @ (1024 x 1024)
    dim3 gproj(Dv / BN, BNROWS / BM, 1);   // (8, 128)
    dim3 blk(NTHREADS);
    sgemm_nn<<<gproj, blk>>>(x, wql, QL, BNROWS, Dv, Dv, 0, 0, 0);
    sgemm_nn<<<gproj, blk>>>(x, wqr, QR, BNROWS, Dv, Dv, 0, 0, 0);
    sgemm_nn<<<gproj, blk>>>(x, wk,  Kb, BNROWS, Dv, Dv, 0, 0, 0);
    sgemm_nn<<<gproj, blk>>>(x, wv,  Vb, BNROWS, Dv, Dv, 0, 0, 0);

    // 2) Gate: q = ql * qr (in-place into QL). 16M elements / 4 per thread.
    long nelem = (long)BNROWS * Dv;
    gate_kernel<<<(unsigned)(nelem / 4 / NTHREADS), NTHREADS>>>(QL, QR);

    // 3) kv[b] = k[b]^T @ v[b]  : M=N=1024, K=4096, batch=4
    dim3 gkv(Dv / BN, Dv / BM, Bv);        // (8, 8, 4)
    sgemm_tn<<<gkv, blk>>>(Kb, Vb, KV, Dv, Dv, Nv,
                           (long)Nv * Dv, (long)Nv * Dv, (long)Dv * Dv);

    // 4) out[b] = q[b] @ kv[b]  : M=4096, N=1024, K=1024, batch=4
    dim3 gout(Dv / BN, Nv / BM, Bv);       // (8, 32, 4)
    sgemm_nn<<<gout, blk>>>(QL, KV, out, Nv, Dv, Dv,
                            (long)Nv * Dv, (long)Dv * Dv, (long)Nv * Dv);
}

// round 3
// speedup vs baseline: 2.8053x; 2.8053x over previous
#include <cuda_runtime.h>
#include <cuda_bf16.h>
#include <cstdint>

// LinearAttention B=4, N=4096, D=1024 fp32
// bf16x3 split (hi/lo, 3 passes) on warp-level mma.sync (base compute_103 ISA).
//   ql=x@Wql, qr=x@Wqr, k=x@Wk, v=x@Wv ; q=ql*qr ; kv[b]=k^T@v ; out[b]=q@kv

#define Bv 4
#define Nv 4096
#define Dv 1024
#define BNROWS (Bv*Nv)            // 16384

#define BM 128
#define BN 128
#define BKB 32                    // bf16 K per stage (64B rows)
#define GT 256                    // 8 warps

#define ASZ  8192                 // one A operand tile (128*32*2)
#define STAGE 32768               // Ah+Al+Bh+Bl
#define SMEM_TOTAL (2*STAGE)      // 64KB

// ------------------------------ scratch -----------------------------------
__device__ __align__(16) __nv_bfloat16 g_XH [(size_t)BNROWS*Dv];
__device__ __align__(16) __nv_bfloat16 g_XL [(size_t)BNROWS*Dv];
__device__ __align__(16) __nv_bfloat16 g_WTH[4][1024*1024];
__device__ __align__(16) __nv_bfloat16 g_WTL[4][1024*1024];
__device__ __align__(16) float         g_Pf [4][(size_t)BNROWS*Dv];   // ql,qr,k,v fp32
__device__ __align__(16) __nv_bfloat16 g_QH [(size_t)BNROWS*Dv];
__device__ __align__(16) __nv_bfloat16 g_QLo[(size_t)BNROWS*Dv];
__device__ __align__(16) __nv_bfloat16 g_KTH[(size_t)Bv*Dv*Nv];
__device__ __align__(16) __nv_bfloat16 g_KTL[(size_t)Bv*Dv*Nv];
__device__ __align__(16) __nv_bfloat16 g_VTH[(size_t)Bv*Dv*Nv];
__device__ __align__(16) __nv_bfloat16 g_VTL[(size_t)Bv*Dv*Nv];
__device__ __align__(16) float         g_KVf[(size_t)Bv*Dv*Dv];
__device__ __align__(16) __nv_bfloat16 g_KVTH[(size_t)Bv*Dv*Dv];
__device__ __align__(16) __nv_bfloat16 g_KVTL[(size_t)Bv*Dv*Dv];

// ------------------------------ helpers ------------------------------------
#define SWZ64(x) ((x) ^ (((x) >> 3) & 0x30))

__device__ __forceinline__ uint32_t s2u(const void* p) {
    uint32_t a;
    asm("{ .reg .u64 t; cvta.to.shared.u64 t, %1; cvt.u32.u64 %0, t; }" : "=r"(a) : "l"(p));
    return a;
}
__device__ __forceinline__ void cpa16(uint32_t dst, const void* src) {
    asm volatile("cp.async.cg.shared.global [%0], [%1], 16;" :: "r"(dst), "l"(src));
}
#define CPC() asm volatile("cp.async.commit_group;" ::: "memory")

__device__ __forceinline__ void ldsm4(uint32_t* r, uint32_t addr) {
    asm volatile("ldmatrix.sync.aligned.m8n8.x4.shared.b16 {%0,%1,%2,%3}, [%4];"
                 : "=r"(r[0]), "=r"(r[1]), "=r"(r[2]), "=r"(r[3]) : "r"(addr));
}
__device__ __forceinline__ void mma16816(float* c, const uint32_t* a, const uint32_t* b) {
    asm volatile(
        "mma.sync.aligned.m16n8k16.row.col.f32.bf16.bf16.f32 "
        "{%0,%1,%2,%3}, {%4,%5,%6,%7}, {%8,%9}, {%0,%1,%2,%3};"
        : "+f"(c[0]), "+f"(c[1]), "+f"(c[2]), "+f"(c[3])
        : "r"(a[0]), "r"(a[1]), "r"(a[2]), "r"(a[3]), "r"(b[0]), "r"(b[1]));
}

// ------------------------------ GEMM kernel --------------------------------
// C[M,N] fp32 = (Ah+Al)[M,K] * ((Bh+Bl)[N,K])^T, all K-major, batched on z.
__global__ __launch_bounds__(GT, 1)
void gemm_bf16x3(const __nv_bfloat16* __restrict__ Ahg, const __nv_bfloat16* __restrict__ Alg,
                 const __nv_bfloat16* __restrict__ Bhg, const __nv_bfloat16* __restrict__ Blg,
                 float* __restrict__ Cg, int M, int N, int Kg,
                 long sA, long sB, long sC)
{
    extern __shared__ char sm[];
    const uint32_t smu = s2u(sm);
    const int tid = threadIdx.x, lane = tid & 31, wid = tid >> 5;
    const int bm = blockIdx.y * BM, bn = blockIdx.x * BN;
    const int wm = (wid & 1) * 64, wn = (wid >> 1) * 32;

    const __nv_bfloat16* Ah = Ahg + (size_t)blockIdx.z * sA;
    const __nv_bfloat16* Al = Alg + (size_t)blockIdx.z * sA;
    const __nv_bfloat16* Bh = Bhg + (size_t)blockIdx.z * sB;
    const __nv_bfloat16* Bl = Blg + (size_t)blockIdx.z * sB;
    float* Cb = Cg + (size_t)blockIdx.z * sC;

    // gmem load indices: 512 16B-chunks per operand tile, 2 per thread
    const int r0 = (tid + 0)   >> 2, cg0 = (tid + 0)   & 3;
    const int r1 = (tid + 256) >> 2, cg1 = (tid + 256) & 3;
    const uint32_t so0 = SWZ64((uint32_t)(r0 * 64 + cg0 * 16));
    const uint32_t so1 = SWZ64((uint32_t)(r1 * 64 + cg1 * 16));

    // ldmatrix fragment offsets (relative to operand tile base)
    uint32_t aoff[2][4], boff[2][2];
    {
        uint32_t arow = (uint32_t)(wm + (lane & 15));
        uint32_t acol = (uint32_t)((lane >> 4) * 16);
        uint32_t brow = (uint32_t)(wn + ((lane >> 4) << 3) + (lane & 7));
        uint32_t bcol = (uint32_t)(((lane >> 3) & 1) * 16);
#pragma unroll
        for (int ks = 0; ks < 2; ks++) {
#pragma unroll
            for (int mi = 0; mi < 4; mi++)
                aoff[ks][mi] = SWZ64((arow + mi * 16) * 64 + ks * 32 + acol);
#pragma unroll
            for (int g = 0; g < 2; g++)
                boff[ks][g] = SWZ64((brow + g * 16) * 64 + ks * 32 + bcol);
        }
    }

    float acc[4][4][4];
#pragma unroll
    for (int mi = 0; mi < 4; mi++)
#pragma unroll
        for (int ni = 0; ni < 4; ni++)
#pragma unroll
            for (int j = 0; j < 4; j++) acc[mi][ni][j] = 0.0f;

    const int nch = Kg / BKB;

    auto load_stage = [&](int c) {
        const uint32_t st = smu + (uint32_t)(c & 1) * STAGE;
        const int k0 = c * BKB;
        cpa16(st + so0,              Ah + (size_t)(bm + r0) * Kg + k0 + cg0 * 8);
        cpa16(st + so1,              Ah + (size_t)(bm + r1) * Kg + k0 + cg1 * 8);
        cpa16(st + ASZ + so0,        Al + (size_t)(bm + r0) * Kg + k0 + cg0 * 8);
        cpa16(st + ASZ + so1,        Al + (size_t)(bm + r1) * Kg + k0 + cg1 * 8);
        cpa16(st + 2 * ASZ + so0,    Bh + (size_t)(bn + r0) * Kg + k0 + cg0 * 8);
        cpa16(st + 2 * ASZ + so1,    Bh + (size_t)(bn + r1) * Kg + k0 + cg1 * 8);
        cpa16(st + 3 * ASZ + so0,    Bl + (size_t)(bn + r0) * Kg + k0 + cg0 * 8);
        cpa16(st + 3 * ASZ + so1,    Bl + (size_t)(bn + r1) * Kg + k0 + cg1 * 8);
    };

    load_stage(0); CPC();

    for (int c = 0; c < nch; ++c) {
        if (c + 1 < nch) {
            load_stage(c + 1); CPC();
            asm volatile("cp.async.wait_group 1;" ::: "memory");
        } else {
            asm volatile("cp.async.wait_group 0;" ::: "memory");
        }
        __syncthreads();

        const uint32_t st = smu + (uint32_t)(c & 1) * STAGE;
#pragma unroll
        for (int ks = 0; ks < 2; ks++) {
            uint32_t ah[4][4], al[4][4], bh[4][2], bl[4][2];
#pragma unroll
            for (int mi = 0; mi < 4; mi++) {
                ldsm4(ah[mi], st + aoff[ks][mi]);
                ldsm4(al[mi], st + ASZ + aoff[ks][mi]);
            }
#pragma unroll
            for (int g = 0; g < 2; g++) {
                uint32_t t[4];
                ldsm4(t, st + 2 * ASZ + boff[ks][g]);
                bh[2*g][0] = t[0]; bh[2*g][1] = t[1];
                bh[2*g+1][0] = t[2]; bh[2*g+1][1] = t[3];
                ldsm4(t, st + 3 * ASZ + boff[ks][g]);
                bl[2*g][0] = t[0]; bl[2*g][1] = t[1];
                bl[2*g+1][0] = t[2]; bl[2*g+1][1] = t[3];
            }
#pragma unroll
            for (int mi = 0; mi < 4; mi++)
#pragma unroll
                for (int ni = 0; ni < 4; ni++) {
                    mma16816(acc[mi][ni], ah[mi], bh[ni]);
                    mma16816(acc[mi][ni], ah[mi], bl[ni]);
                    mma16816(acc[mi][ni], al[mi], bh[ni]);
                }
        }
        __syncthreads();
    }

    // epilogue: m16n8 fragment -> C
#pragma unroll
    for (int mi = 0; mi < 4; mi++) {
        int rA = bm + wm + mi * 16 + (lane >> 2);
#pragma unroll
        for (int ni = 0; ni < 4; ni++) {
            int col = bn + wn + ni * 8 + (lane & 3) * 2;
            *(float2*)(Cb + (size_t)rA * N + col)       = make_float2(acc[mi][ni][0], acc[mi][ni][1]);
            *(float2*)(Cb + (size_t)(rA + 8) * N + col) = make_float2(acc[mi][ni][2], acc[mi][ni][3]);
        }
    }
}

// --------------------------- conversion kernels ----------------------------
__device__ __forceinline__ void split1(float f, __nv_bfloat16& h, __nv_bfloat16& l) {
    h = __float2bfloat16(f);
    l = __float2bfloat16(f - __bfloat162float(h));
}

__global__ void split_plain(const float* __restrict__ in,
                            __nv_bfloat16* __restrict__ oh, __nv_bfloat16* __restrict__ ol) {
    size_t i = (size_t)blockIdx.x * blockDim.x + threadIdx.x;
    float4 f = ((const float4*)in)[i];
    __nv_bfloat16 h0,h1,h2,h3,l0,l1,l2,l3;
    split1(f.x,h0,l0); split1(f.y,h1,l1); split1(f.z,h2,l2); split1(f.w,h3,l3);
    ((__nv_bfloat162*)oh)[i*2]   = __halves2bfloat162(h0,h1);
    ((__nv_bfloat162*)oh)[i*2+1] = __halves2bfloat162(h2,h3);
    ((__nv_bfloat162*)ol)[i*2]   = __halves2bfloat162(l0,l1);
    ((__nv_bfloat162*)ol)[i*2+1] = __halves2bfloat162(l2,l3);
}

__global__ void gate_split(const float* __restrict__ a, const float* __restrict__ b,
                           __nv_bfloat16* __restrict__ oh, __nv_bfloat16* __restrict__ ol) {
    size_t i = (size_t)blockIdx.x * blockDim.x + threadIdx.x;
    float4 fa = ((const float4*)a)[i];
    float4 fb = ((const float4*)b)[i];
    fa.x *= fb.x; fa.y *= fb.y; fa.z *= fb.z; fa.w *= fb.w;
    __nv_bfloat16 h0,h1,h2,h3,l0,l1,l2,l3;
    split1(fa.x,h0,l0); split1(fa.y,h1,l1); split1(fa.z,h2,l2); split1(fa.w,h3,l3);
    ((__nv_bfloat162*)oh)[i*2]   = __halves2bfloat162(h0,h1);
    ((__nv_bfloat162*)oh)[i*2+1] = __halves2bfloat162(h2,h3);
    ((__nv_bfloat162*)ol)[i*2]   = __halves2bfloat162(l0,l1);
    ((__nv_bfloat162*)ol)[i*2+1] = __halves2bfloat162(l2,l3);
}

// in [R,C] fp32 (batch z) -> out [C,R] bf16 hi/lo
__global__ void split_transpose(const float* __restrict__ in,
                                __nv_bfloat16* __restrict__ oh, __nv_bfloat16* __restrict__ ol,
                                int R, int Cc, long sIn, long sOut) {
    __shared__ float t[32][33];
    const float* ib = in + (size_t)blockIdx.z * sIn;
    __nv_bfloat16* ohb = oh + (size_t)blockIdx.z * sOut;
    __nv_bfloat16* olb = ol + (size_t)blockIdx.z * sOut;
    int c0 = blockIdx.x * 32, r0 = blockIdx.y * 32;
    int tx = threadIdx.x, ty = threadIdx.y;
#pragma unroll
    for (int i = 0; i < 4; i++)
        t[ty + i*8][tx] = ib[(size_t)(r0 + ty + i*8) * Cc + c0 + tx];
    __syncthreads();
#pragma unroll
    for (int i = 0; i < 4; i++) {
        int oc = c0 + ty + i*8, orow = r0 + tx;
        float f = t[tx][ty + i*8];
        __nv_bfloat16 h, l; split1(f, h, l);
        ohb[(size_t)oc * R + orow] = h;
        olb[(size_t)oc * R + orow] = l;
    }
}

// ------------------------------- launch ------------------------------------
extern "C" void kernel_launch(void* const* d_in, const int* in_sizes, int n_in,
                              void* d_out, int out_size) {
    const float* x   = (const float*)d_in[0];
    const float* w[4] = { (const float*)d_in[1], (const float*)d_in[2],
                          (const float*)d_in[3], (const float*)d_in[4] };
    float* out = (float*)d_out;

    __nv_bfloat16 *XH,*XL,*WTH,*WTL,*QH,*QLo,*KTH,*KTL,*VTH,*VTL,*KVTH,*KVTL;
    float *Pf,*KVf;
    cudaGetSymbolAddress((void**)&XH,  g_XH);   cudaGetSymbolAddress((void**)&XL,  g_XL);
    cudaGetSymbolAddress((void**)&WTH, g_WTH);  cudaGetSymbolAddress((void**)&WTL, g_WTL);
    cudaGetSymbolAddress((void**)&Pf,  g_Pf);
    cudaGetSymbolAddress((void**)&QH,  g_QH);   cudaGetSymbolAddress((void**)&QLo, g_QLo);
    cudaGetSymbolAddress((void**)&KTH, g_KTH);  cudaGetSymbolAddress((void**)&KTL, g_KTL);
    cudaGetSymbolAddress((void**)&VTH, g_VTH);  cudaGetSymbolAddress((void**)&VTL, g_VTL);
    cudaGetSymbolAddress((void**)&KVf, g_KVf);
    cudaGetSymbolAddress((void**)&KVTH,g_KVTH); cudaGetSymbolAddress((void**)&KVTL,g_KVTL);

    cudaFuncSetAttribute(gemm_bf16x3, cudaFuncAttributeMaxDynamicSharedMemorySize, SMEM_TOTAL);

    const size_t DDe = (size_t)Dv * Dv;
    const size_t PNe = (size_t)BNROWS * Dv;
    dim3 tb32(32, 8);

    // 1) splits of x and W^T
    split_plain<<<(unsigned)(PNe/4/256), 256>>>(x, XH, XL);
    for (int i = 0; i < 4; i++)
        split_transpose<<<dim3(Dv/32, Dv/32, 1), tb32>>>(w[i], WTH + i*DDe, WTL + i*DDe,
                                                         Dv, Dv, 0, 0);
    // 2) projections: [16384,1024] = X @ W  (B operand = W^T, K-major)
    dim3 gproj(Dv/BN, BNROWS/BM, 1);
    for (int i = 0; i < 4; i++)
        gemm_bf16x3<<<gproj, GT, SMEM_TOTAL>>>(XH, XL, WTH + i*DDe, WTL + i*DDe,
                                               Pf + i*PNe, BNROWS, Dv, Dv, 0, 0, 0);
    float* QLf = Pf;          float* QRf = Pf + PNe;
    float* Kf  = Pf + 2*PNe;  float* Vf  = Pf + 3*PNe;

    // 3) gate + split q
    gate_split<<<(unsigned)(PNe/4/256), 256>>>(QLf, QRf, QH, QLo);

    // 4) transpose-splits of k, v  ([Nv,Dv] -> [Dv,Nv] per batch)
    split_transpose<<<dim3(Dv/32, Nv/32, Bv), tb32>>>(Kf, KTH, KTL, Nv, Dv,
                                                      (long)Nv*Dv, (long)Nv*Dv);
    split_transpose<<<dim3(Dv/32, Nv/32, Bv), tb32>>>(Vf, VTH, VTL, Nv, Dv,
                                                      (long)Nv*Dv, (long)Nv*Dv);
    // 5) kv[b] = k^T @ v : A=kT[Dv,Nv], B=vT[Dv,Nv] (both K(=Nv)-major)
    gemm_bf16x3<<<dim3(Dv/BN, Dv/BM, Bv), GT, SMEM_TOTAL>>>(
        KTH, KTL, VTH, VTL, KVf, Dv, Dv, Nv,
        (long)Dv*Nv, (long)Dv*Nv, (long)DDe);

    // 6) transpose-split kv ([Dv,Dv] -> [Dv,Dv]^T per batch)
    split_transpose<<<dim3(Dv/32, Dv/32, Bv), tb32>>>(KVf, KVTH, KVTL, Dv, Dv,
                                                      (long)DDe, (long)DDe);
    // 7) out[b] = q @ kv : A=q[Nv,Dv], B=kv^T[Dv,Dv] (K(=Dv)-major)
    gemm_bf16x3<<<dim3(Dv/BN, Nv/BM, Bv), GT, SMEM_TOTAL>>>(
        QH, QLo, KVTH, KVTL, out, Nv, Dv, Dv,
        (long)Nv*Dv, (long)DDe, (long)Nv*Dv);
}

// round 4
// speedup vs baseline: 2.9270x; 1.0434x over previous
#include <cuda_runtime.h>
#include <cuda_bf16.h>
#include <cstdint>

// LinearAttention B=4, N=4096, D=1024 fp32
// bf16x3 split (hi/lo, 3 passes) on warp-level mma.sync (base compute_103 ISA).
// Round 4: 4-stage cp.async pipeline, reduced register pressure, batched projections.

#define Bv 4
#define Nv 4096
#define Dv 1024
#define BNROWS (Bv*Nv)            // 16384

#define BM 128
#define BN 128
#define BKB 32                    // bf16 K per stage (64B rows)
#define GT 256                    // 8 warps

#define ASZ   8192                // one operand tile (128*32*2B)
#define STAGE 32768               // Ah+Al+Bh+Bl
#define NSTG  4
#define SMEM_TOTAL (NSTG*STAGE)   // 128KB

// ------------------------------ scratch -----------------------------------
__device__ __align__(16) __nv_bfloat16 g_XH [(size_t)BNROWS*Dv];
__device__ __align__(16) __nv_bfloat16 g_XL [(size_t)BNROWS*Dv];
__device__ __align__(16) __nv_bfloat16 g_WTH[4][1024*1024];
__device__ __align__(16) __nv_bfloat16 g_WTL[4][1024*1024];
__device__ __align__(16) float         g_Pf [4][(size_t)BNROWS*Dv];   // ql,qr,k,v fp32
__device__ __align__(16) __nv_bfloat16 g_QH [(size_t)BNROWS*Dv];
__device__ __align__(16) __nv_bfloat16 g_QLo[(size_t)BNROWS*Dv];
__device__ __align__(16) __nv_bfloat16 g_KTH[(size_t)Bv*Dv*Nv];
__device__ __align__(16) __nv_bfloat16 g_KTL[(size_t)Bv*Dv*Nv];
__device__ __align__(16) __nv_bfloat16 g_VTH[(size_t)Bv*Dv*Nv];
__device__ __align__(16) __nv_bfloat16 g_VTL[(size_t)Bv*Dv*Nv];
__device__ __align__(16) float         g_KVf[(size_t)Bv*Dv*Dv];
__device__ __align__(16) __nv_bfloat16 g_KVTH[(size_t)Bv*Dv*Dv];
__device__ __align__(16) __nv_bfloat16 g_KVTL[(size_t)Bv*Dv*Dv];

// ------------------------------ helpers ------------------------------------
#define SWZ64(x) ((x) ^ (((x) >> 3) & 0x30))

__device__ __forceinline__ uint32_t s2u(const void* p) {
    uint32_t a;
    asm("{ .reg .u64 t; cvta.to.shared.u64 t, %1; cvt.u32.u64 %0, t; }" : "=r"(a) : "l"(p));
    return a;
}
__device__ __forceinline__ void cpa16(uint32_t dst, const void* src) {
    asm volatile("cp.async.cg.shared.global [%0], [%1], 16;" :: "r"(dst), "l"(src));
}
#define CPC() asm volatile("cp.async.commit_group;" ::: "memory")

__device__ __forceinline__ void ldsm4(uint32_t* r, uint32_t addr) {
    asm volatile("ldmatrix.sync.aligned.m8n8.x4.shared.b16 {%0,%1,%2,%3}, [%4];"
                 : "=r"(r[0]), "=r"(r[1]), "=r"(r[2]), "=r"(r[3]) : "r"(addr));
}
__device__ __forceinline__ void mma16816(float* c, const uint32_t* a, const uint32_t* b) {
    asm volatile(
        "mma.sync.aligned.m16n8k16.row.col.f32.bf16.bf16.f32 "
        "{%0,%1,%2,%3}, {%4,%5,%6,%7}, {%8,%9}, {%0,%1,%2,%3};"
        : "+f"(c[0]), "+f"(c[1]), "+f"(c[2]), "+f"(c[3])
        : "r"(a[0]), "r"(a[1]), "r"(a[2]), "r"(a[3]), "r"(b[0]), "r"(b[1]));
}

// ------------------------------ GEMM kernel --------------------------------
// C[M,N] fp32 = (Ah+Al)[M,K] * ((Bh+Bl)[N,K])^T, all K-major, batched on z.
__global__ __launch_bounds__(GT, 1)
void gemm_bf16x3(const __nv_bfloat16* __restrict__ Ahg, const __nv_bfloat16* __restrict__ Alg,
                 const __nv_bfloat16* __restrict__ Bhg, const __nv_bfloat16* __restrict__ Blg,
                 float* __restrict__ Cg, int M, int N, int Kg,
                 long sA, long sB, long sC)
{
    extern __shared__ char sm[];
    const uint32_t smu = s2u(sm);
    const int tid = threadIdx.x, lane = tid & 31, wid = tid >> 5;
    const int bm = blockIdx.y * BM, bn = blockIdx.x * BN;
    const int wm = (wid & 1) * 64, wn = (wid >> 1) * 32;

    const __nv_bfloat16* Ah = Ahg + (size_t)blockIdx.z * sA;
    const __nv_bfloat16* Al = Alg + (size_t)blockIdx.z * sA;
    const __nv_bfloat16* Bh = Bhg + (size_t)blockIdx.z * sB;
    const __nv_bfloat16* Bl = Blg + (size_t)blockIdx.z * sB;
    float* Cb = Cg + (size_t)blockIdx.z * sC;

    // gmem load indices: 512 16B-chunks per operand tile, 2 per thread
    const int r0 = (tid + 0)   >> 2, cg0 = (tid + 0)   & 3;
    const int r1 = (tid + 256) >> 2, cg1 = (tid + 256) & 3;
    const uint32_t so0 = SWZ64((uint32_t)(r0 * 64 + cg0 * 16));
    const uint32_t so1 = SWZ64((uint32_t)(r1 * 64 + cg1 * 16));
    const __nv_bfloat16* gA0 = Ah + (size_t)(bm + r0) * Kg + cg0 * 8;
    const __nv_bfloat16* gA1 = Ah + (size_t)(bm + r1) * Kg + cg1 * 8;
    const __nv_bfloat16* gAl0 = Al + (size_t)(bm + r0) * Kg + cg0 * 8;
    const __nv_bfloat16* gAl1 = Al + (size_t)(bm + r1) * Kg + cg1 * 8;
    const __nv_bfloat16* gB0 = Bh + (size_t)(bn + r0) * Kg + cg0 * 8;
    const __nv_bfloat16* gB1 = Bh + (size_t)(bn + r1) * Kg + cg1 * 8;
    const __nv_bfloat16* gBl0 = Bl + (size_t)(bn + r0) * Kg + cg0 * 8;
    const __nv_bfloat16* gBl1 = Bl + (size_t)(bn + r1) * Kg + cg1 * 8;

    // ldmatrix fragment offsets (relative to operand tile base)
    uint32_t aoff[2][4], boff[2][2];
    {
        uint32_t arow = (uint32_t)(wm + (lane & 15));
        uint32_t acol = (uint32_t)((lane >> 4) * 16);
        uint32_t brow = (uint32_t)(wn + ((lane >> 4) << 3) + (lane & 7));
        uint32_t bcol = (uint32_t)(((lane >> 3) & 1) * 16);
#pragma unroll
        for (int ks = 0; ks < 2; ks++) {
#pragma unroll
            for (int mi = 0; mi < 4; mi++)
                aoff[ks][mi] = SWZ64((arow + mi * 16) * 64 + ks * 32 + acol);
#pragma unroll
            for (int g = 0; g < 2; g++)
                boff[ks][g] = SWZ64((brow + g * 16) * 64 + ks * 32 + bcol);
        }
    }

    float acc[4][4][4];
#pragma unroll
    for (int mi = 0; mi < 4; mi++)
#pragma unroll
        for (int ni = 0; ni < 4; ni++)
#pragma unroll
            for (int j = 0; j < 4; j++) acc[mi][ni][j] = 0.0f;

    const int nch = Kg / BKB;

    auto load_stage = [&](int c) {
        const uint32_t st = smu + (uint32_t)(c & (NSTG - 1)) * STAGE;
        const int k0 = c * BKB;
        cpa16(st + so0,           gA0  + k0);
        cpa16(st + so1,           gA1  + k0);
        cpa16(st + ASZ + so0,     gAl0 + k0);
        cpa16(st + ASZ + so1,     gAl1 + k0);
        cpa16(st + 2*ASZ + so0,   gB0  + k0);
        cpa16(st + 2*ASZ + so1,   gB1  + k0);
        cpa16(st + 3*ASZ + so0,   gBl0 + k0);
        cpa16(st + 3*ASZ + so1,   gBl1 + k0);
        CPC();
    };

    load_stage(0);
    load_stage(1);
    load_stage(2);

    for (int c = 0; c < nch; ++c) {
        asm volatile("cp.async.wait_group 2;" ::: "memory");
        __syncthreads();
        if (c + 3 < nch) load_stage(c + 3);

        const uint32_t st = smu + (uint32_t)(c & (NSTG - 1)) * STAGE;
#pragma unroll
        for (int ks = 0; ks < 2; ks++) {
            uint32_t ah[4][4], al[4][4];
#pragma unroll
            for (int mi = 0; mi < 4; mi++) {
                ldsm4(ah[mi], st + aoff[ks][mi]);
                ldsm4(al[mi], st + ASZ + aoff[ks][mi]);
            }
#pragma unroll
            for (int g = 0; g < 2; g++) {
                uint32_t tbh[4], tbl[4];
                ldsm4(tbh, st + 2*ASZ + boff[ks][g]);
                ldsm4(tbl, st + 3*ASZ + boff[ks][g]);
#pragma unroll
                for (int mi = 0; mi < 4; mi++) {
                    mma16816(acc[mi][2*g],   ah[mi], tbh);
                    mma16816(acc[mi][2*g],   ah[mi], tbl);
                    mma16816(acc[mi][2*g],   al[mi], tbh);
                    mma16816(acc[mi][2*g+1], ah[mi], tbh + 2);
                    mma16816(acc[mi][2*g+1], ah[mi], tbl + 2);
                    mma16816(acc[mi][2*g+1], al[mi], tbh + 2);
                }
            }
        }
    }

    // epilogue: m16n8 fragment -> C
#pragma unroll
    for (int mi = 0; mi < 4; mi++) {
        int rA = bm + wm + mi * 16 + (lane >> 2);
#pragma unroll
        for (int ni = 0; ni < 4; ni++) {
            int col = bn + wn + ni * 8 + (lane & 3) * 2;
            *(float2*)(Cb + (size_t)rA * N + col)       = make_float2(acc[mi][ni][0], acc[mi][ni][1]);
            *(float2*)(Cb + (size_t)(rA + 8) * N + col) = make_float2(acc[mi][ni][2], acc[mi][ni][3]);
        }
    }
}

// --------------------------- conversion kernels ----------------------------
__device__ __forceinline__ void split1(float f, __nv_bfloat16& h, __nv_bfloat16& l) {
    h = __float2bfloat16(f);
    l = __float2bfloat16(f - __bfloat162float(h));
}

__global__ void split_plain(const float* __restrict__ in,
                            __nv_bfloat16* __restrict__ oh, __nv_bfloat16* __restrict__ ol) {
    size_t i = (size_t)blockIdx.x * blockDim.x + threadIdx.x;
    float4 f = ((const float4*)in)[i];
    __nv_bfloat16 h0,h1,h2,h3,l0,l1,l2,l3;
    split1(f.x,h0,l0); split1(f.y,h1,l1); split1(f.z,h2,l2); split1(f.w,h3,l3);
    ((__nv_bfloat162*)oh)[i*2]   = __halves2bfloat162(h0,h1);
    ((__nv_bfloat162*)oh)[i*2+1] = __halves2bfloat162(h2,h3);
    ((__nv_bfloat162*)ol)[i*2]   = __halves2bfloat162(l0,l1);
    ((__nv_bfloat162*)ol)[i*2+1] = __halves2bfloat162(l2,l3);
}

__global__ void gate_split(const float* __restrict__ a, const float* __restrict__ b,
                           __nv_bfloat16* __restrict__ oh, __nv_bfloat16* __restrict__ ol) {
    size_t i = (size_t)blockIdx.x * blockDim.x + threadIdx.x;
    float4 fa = ((const float4*)a)[i];
    float4 fb = ((const float4*)b)[i];
    fa.x *= fb.x; fa.y *= fb.y; fa.z *= fb.z; fa.w *= fb.w;
    __nv_bfloat16 h0,h1,h2,h3,l0,l1,l2,l3;
    split1(fa.x,h0,l0); split1(fa.y,h1,l1); split1(fa.z,h2,l2); split1(fa.w,h3,l3);
    ((__nv_bfloat162*)oh)[i*2]   = __halves2bfloat162(h0,h1);
    ((__nv_bfloat162*)oh)[i*2+1] = __halves2bfloat162(h2,h3);
    ((__nv_bfloat162*)ol)[i*2]   = __halves2bfloat162(l0,l1);
    ((__nv_bfloat162*)ol)[i*2+1] = __halves2bfloat162(l2,l3);
}

// in [R,C] fp32 (batch z) -> out [C,R] bf16 hi/lo
__global__ void split_transpose(const float* __restrict__ in,
                                __nv_bfloat16* __restrict__ oh, __nv_bfloat16* __restrict__ ol,
                                int R, int Cc, long sIn, long sOut) {
    __shared__ float t[32][33];
    const float* ib = in + (size_t)blockIdx.z * sIn;
    __nv_bfloat16* ohb = oh + (size_t)blockIdx.z * sOut;
    __nv_bfloat16* olb = ol + (size_t)blockIdx.z * sOut;
    int c0 = blockIdx.x * 32, r0 = blockIdx.y * 32;
    int tx = threadIdx.x, ty = threadIdx.y;
#pragma unroll
    for (int i = 0; i < 4; i++)
        t[ty + i*8][tx] = ib[(size_t)(r0 + ty + i*8) * Cc + c0 + tx];
    __syncthreads();
#pragma unroll
    for (int i = 0; i < 4; i++) {
        int oc = c0 + ty + i*8, orow = r0 + tx;
        float f = t[tx][ty + i*8];
        __nv_bfloat16 h, l; split1(f, h, l);
        ohb[(size_t)oc * R + orow] = h;
        olb[(size_t)oc * R + orow] = l;
    }
}

// ------------------------------- launch ------------------------------------
extern "C" void kernel_launch(void* const* d_in, const int* in_sizes, int n_in,
                              void* d_out, int out_size) {
    const float* x   = (const float*)d_in[0];
    const float* w[4] = { (const float*)d_in[1], (const float*)d_in[2],
                          (const float*)d_in[3], (const float*)d_in[4] };
    float* out = (float*)d_out;

    __nv_bfloat16 *XH,*XL,*WTH,*WTL,*QH,*QLo,*KTH,*KTL,*VTH,*VTL,*KVTH,*KVTL;
    float *Pf,*KVf;
    cudaGetSymbolAddress((void**)&XH,  g_XH);   cudaGetSymbolAddress((void**)&XL,  g_XL);
    cudaGetSymbolAddress((void**)&WTH, g_WTH);  cudaGetSymbolAddress((void**)&WTL, g_WTL);
    cudaGetSymbolAddress((void**)&Pf,  g_Pf);
    cudaGetSymbolAddress((void**)&QH,  g_QH);   cudaGetSymbolAddress((void**)&QLo, g_QLo);
    cudaGetSymbolAddress((void**)&KTH, g_KTH);  cudaGetSymbolAddress((void**)&KTL, g_KTL);
    cudaGetSymbolAddress((void**)&VTH, g_VTH);  cudaGetSymbolAddress((void**)&VTL, g_VTL);
    cudaGetSymbolAddress((void**)&KVf, g_KVf);
    cudaGetSymbolAddress((void**)&KVTH,g_KVTH); cudaGetSymbolAddress((void**)&KVTL,g_KVTL);

    cudaFuncSetAttribute(gemm_bf16x3, cudaFuncAttributeMaxDynamicSharedMemorySize, SMEM_TOTAL);

    const size_t DDe = (size_t)Dv * Dv;
    const size_t PNe = (size_t)BNROWS * Dv;
    dim3 tb32(32, 8);

    // 1) splits of x and W^T
    split_plain<<<(unsigned)(PNe/4/256), 256>>>(x, XH, XL);
    for (int i = 0; i < 4; i++)
        split_transpose<<<dim3(Dv/32, Dv/32, 1), tb32>>>(w[i], WTH + i*DDe, WTL + i*DDe,
                                                         Dv, Dv, 0, 0);
    // 2) all 4 projections in ONE launch: z indexes weight (sB=DDe) and output (sC=PNe)
    gemm_bf16x3<<<dim3(Dv/BN, BNROWS/BM, 4), GT, SMEM_TOTAL>>>(
        XH, XL, (const __nv_bfloat16*)WTH, (const __nv_bfloat16*)WTL,
        Pf, BNROWS, Dv, Dv, 0, (long)DDe, (long)PNe);

    float* QLf = Pf;          float* QRf = Pf + PNe;
    float* Kf  = Pf + 2*PNe;  float* Vf  = Pf + 3*PNe;

    // 3) gate + split q
    gate_split<<<(unsigned)(PNe/4/256), 256>>>(QLf, QRf, QH, QLo);

    // 4) transpose-splits of k, v  ([Nv,Dv] -> [Dv,Nv] per batch)
    split_transpose<<<dim3(Dv/32, Nv/32, Bv), tb32>>>(Kf, KTH, KTL, Nv, Dv,
                                                      (long)Nv*Dv, (long)Nv*Dv);
    split_transpose<<<dim3(Dv/32, Nv/32, Bv), tb32>>>(Vf, VTH, VTL, Nv, Dv,
                                                      (long)Nv*Dv, (long)Nv*Dv);
    // 5) kv[b] = k^T @ v : A=kT[Dv,Nv], B=vT[Dv,Nv] (both K(=Nv)-major)
    gemm_bf16x3<<<dim3(Dv/BN, Dv/BM, Bv), GT, SMEM_TOTAL>>>(
        KTH, KTL, VTH, VTL, KVf, Dv, Dv, Nv,
        (long)Dv*Nv, (long)Dv*Nv, (long)DDe);

    // 6) transpose-split kv ([Dv,Dv] -> [Dv,Dv]^T per batch)
    split_transpose<<<dim3(Dv/32, Dv/32, Bv), tb32>>>(KVf, KVTH, KVTL, Dv, Dv,
                                                      (long)DDe, (long)DDe);
    // 7) out[b] = q @ kv : A=q[Nv,Dv], B=kv^T[Dv,Dv] (K(=Dv)-major)
    gemm_bf16x3<<<dim3(Dv/BN, Nv/BM, Bv), GT, SMEM_TOTAL>>>(
        QH, QLo, KVTH, KVTL, out, Nv, Dv, Dv,
        (long)Nv*Dv, (long)DDe, (long)Nv*Dv);
}